// round 4
// baseline (speedup 1.0000x reference)
#include <cuda_runtime.h>

// HawkesKT — table-collapsed, float2-packed, occupancy-optimized.
// G[c][e] = (alpha, -clip(beta+1,0,10)/ln5); main kernel:
//   sum_{i<j} ga * exp2(gb * log2(|ti-tj| + 1e-10))

#define NJ 8          // j-columns per CTA
#define RS 9          // Gs row stride in float2 units (conflict-free-ish, float2-aligned)

__device__ float2 g_pack[256 * 512];   // [c][e] -> (ga, gb)

// ---------------- Precompute: C[512e x 256c] dual GEMM into packed table ----------------
__global__ __launch_bounds__(256)
void precompute_kernel(const float* __restrict__ a_inter,    // [512,64]
                       const float* __restrict__ a_concept,  // [256,64]
                       const float* __restrict__ b_inter,    // [512,64]
                       const float* __restrict__ b_concept)  // [256,64]
{
    __shared__ float4 ai[16][16], bi[16][16];   // [e_local][d4]
    const int e0  = blockIdx.x * 16;
    const int tid = threadIdx.x;
    {   // 256 float4 per table, one per thread
        int e = tid >> 4, d4 = tid & 15;
        ai[e][d4] = ((const float4*)a_inter)[(e0 + e) * 16 + d4];
        bi[e][d4] = ((const float4*)b_inter)[(e0 + e) * 16 + d4];
    }
    __syncthreads();

    const int c = tid;
    float acc_a[16], acc_b[16];
    #pragma unroll
    for (int e = 0; e < 16; e++) { acc_a[e] = 0.f; acc_b[e] = 0.f; }

    #pragma unroll
    for (int d4 = 0; d4 < 16; d4++) {
        float4 av = ((const float4*)a_concept)[c * 16 + d4];
        float4 bv = ((const float4*)b_concept)[c * 16 + d4];
        #pragma unroll
        for (int e = 0; e < 16; e++) {
            float4 u = ai[e][d4];   // broadcast LDS
            float4 w = bi[e][d4];
            acc_a[e] = fmaf(av.x, u.x, fmaf(av.y, u.y, fmaf(av.z, u.z, fmaf(av.w, u.w, acc_a[e]))));
            acc_b[e] = fmaf(bv.x, w.x, fmaf(bv.y, w.y, fmaf(bv.z, w.z, fmaf(bv.w, w.w, acc_b[e]))));
        }
    }
    #pragma unroll
    for (int e = 0; e < 16; e++) {
        float beta = fminf(fmaxf(acc_b[e] + 1.0f, 0.0f), 10.0f);
        g_pack[c * 512 + e0 + e] = make_float2(acc_a[e], -beta * 0.62133497f);  // -beta/ln5
    }
}

// ---------------- Main: causal elementwise sum ----------------
__global__ __launch_bounds__(256)
void hawkes_main(const int* __restrict__ concept_seq,      // [32,1024]
                 const int* __restrict__ question_seq,     // [32,1024]
                 const int* __restrict__ correctness_seq,  // [32,1024]
                 const int* __restrict__ time_seq,         // [32,1024]
                 const float* __restrict__ q_bias,         // [10000]
                 const float* __restrict__ c_bias,         // [256]
                 float* __restrict__ out)                  // [32,1023]
{
    constexpr int SEQ = 1024;
    extern __shared__ float2 sm2[];
    float2* Gs   = sm2;                  // [512][RS] -> (ga, gb) per (e, j-lane)
    float2* tse  = Gs + 512 * RS;        // [1024]    -> (time, e*RS as int bits)
    float*  jred = (float*)(tse + SEQ);  // [NJ]

    const int b   = blockIdx.y;
    const int j0  = ((int)gridDim.x - 1 - (int)blockIdx.x) * NJ;  // big tiles launch first
    const int tid = threadIdx.x;
    const int tj  = tid & (NJ - 1);      // 0..7
    const int si  = tid >> 3;            // 0..31

    // Stage (time, row-offset) pairs for the whole sequence
    for (int i = tid; i < SEQ; i += 256) {
        int g = b * SEQ + i;
        int e = concept_seq[g] + (correctness_seq[g] << 8);
        tse[i] = make_float2((float)time_seq[g], __int_as_float(e * RS));
    }
    if (tid < NJ) jred[tid] = 0.0f;

    // Gather packed rows for this CTA's NJ concepts: Gs[e][jl] <- g_pack[c_j][e]
    for (int idx = tid; idx < NJ * 256; idx += 256) {
        int jl = idx >> 8;               // 0..7
        int q  = idx & 255;              // float4 index (2 float2 entries)
        int cj = concept_seq[b * SEQ + j0 + jl];
        float4 v = ((const float4*)(g_pack + cj * 512))[q];
        Gs[(2 * q + 0) * RS + jl] = make_float2(v.x, v.y);
        Gs[(2 * q + 1) * RS + jl] = make_float2(v.z, v.w);
    }
    __syncthreads();

    const int   jg  = j0 + tj;
    const float tjv = tse[jg].x;
    const int iend  = j0 + NJ;
    float jsum = 0.0f;

    #pragma unroll 4
    for (int i = si; i < iend; i += 32) {
        float2 tv = tse[i];                              // LDS.64 (half-warp broadcast)
        float2 g  = Gs[__float_as_int(tv.y) + tj];       // LDS.64, conflict-free-ish
        float dt = fabsf(tv.x - tjv);
        float lg = __log2f(dt + 1e-10f);
        float ex = exp2f(g.y * lg);                      // = exp(-beta*log5(dt))
        jsum += (i < jg) ? g.x * ex : 0.0f;
    }

    // Reduce 32 i-slots -> per-j: fold groups within warp, then smem atomics
    jsum += __shfl_down_sync(0xffffffffu, jsum, 16);
    jsum += __shfl_down_sync(0xffffffffu, jsum, 8);
    if ((tid & 31) < NJ) atomicAdd(&jred[tj], jsum);
    __syncthreads();

    // Epilogue: bias + sigmoid; output drops j=0
    if (tid < NJ) {
        int j = j0 + tid;
        if (j > 0) {
            float x = q_bias[question_seq[b * SEQ + j]]
                    + c_bias[concept_seq[b * SEQ + j]]
                    + jred[tid];
            out[b * (SEQ - 1) + (j - 1)] = 1.0f / (1.0f + __expf(-x));
        }
    }
}

extern "C" void kernel_launch(void* const* d_in, const int* in_sizes, int n_in,
                              void* d_out, int out_size)
{
    (void)in_sizes; (void)n_in; (void)out_size;
    const int*   concept_seq     = (const int*)  d_in[0];
    const int*   question_seq    = (const int*)  d_in[1];
    const int*   correctness_seq = (const int*)  d_in[2];
    const int*   time_seq        = (const int*)  d_in[3];
    const float* a_inter         = (const float*)d_in[4];
    const float* a_concept       = (const float*)d_in[5];
    const float* b_inter         = (const float*)d_in[6];
    const float* b_concept       = (const float*)d_in[7];
    const float* q_bias          = (const float*)d_in[8];
    const float* c_bias          = (const float*)d_in[9];
    float* out = (float*)d_out;

    precompute_kernel<<<32, 256>>>(a_inter, a_concept, b_inter, b_concept);

    const int smem_bytes = (512 * RS + 1024) * (int)sizeof(float2) + NJ * (int)sizeof(float);
    cudaFuncSetAttribute(hawkes_main,
                         cudaFuncAttributeMaxDynamicSharedMemorySize, smem_bytes);
    dim3 grid(1024 / NJ, 32);   // (j-tiles, batches)
    hawkes_main<<<grid, 256, smem_bytes>>>(
        concept_seq, question_seq, correctness_seq, time_seq,
        q_bias, c_bias, out);
}

// round 6
// speedup vs baseline: 1.7383x; 1.7383x over previous
#include <cuda_runtime.h>

// HawkesKT — table-collapsed, float2-packed, fast-MUFU inner loop.
// G[c][e] = (alpha, -clip(beta+1,0,10)/ln5); main kernel computes
//   sum_{i<j} ga * 2^(gb * log2(|ti-tj| + 1e-10))  via one LG2 + one EX2 per pair.

#define NJ 8          // j-columns per CTA
#define RS 9          // Gs row stride in float2 units (conflict-free, float2-aligned)

__device__ float2 g_pack[256 * 512];   // [c][e] -> (ga, gb)

__device__ __forceinline__ float fast_ex2(float x) {
    float r;
    asm("ex2.approx.f32 %0, %1;" : "=f"(r) : "f"(x));
    return r;
}

// ---------------- Precompute: dual 512x256x64 GEMM into packed table (128 CTAs) ----------------
__global__ __launch_bounds__(256)
void precompute_kernel(const float* __restrict__ a_inter,    // [512,64]
                       const float* __restrict__ a_concept,  // [256,64]
                       const float* __restrict__ b_inter,    // [512,64]
                       const float* __restrict__ b_concept)  // [256,64]
{
    __shared__ float4 ai[4][16], bi[4][16];   // [e_local][d4]
    const int e0  = blockIdx.x * 4;
    const int tid = threadIdx.x;
    if (tid < 64) {
        ai[tid >> 4][tid & 15] = ((const float4*)a_inter)[(e0 + (tid >> 4)) * 16 + (tid & 15)];
    } else if (tid < 128) {
        int t = tid - 64;
        bi[t >> 4][t & 15] = ((const float4*)b_inter)[(e0 + (t >> 4)) * 16 + (t & 15)];
    }
    __syncthreads();

    const int c = tid;
    float acc_a[4] = {0.f, 0.f, 0.f, 0.f};
    float acc_b[4] = {0.f, 0.f, 0.f, 0.f};

    #pragma unroll
    for (int d4 = 0; d4 < 16; d4++) {
        float4 av = ((const float4*)a_concept)[c * 16 + d4];
        float4 bv = ((const float4*)b_concept)[c * 16 + d4];
        #pragma unroll
        for (int e = 0; e < 4; e++) {
            float4 u = ai[e][d4];   // broadcast LDS
            float4 w = bi[e][d4];
            acc_a[e] = fmaf(av.x, u.x, fmaf(av.y, u.y, fmaf(av.z, u.z, fmaf(av.w, u.w, acc_a[e]))));
            acc_b[e] = fmaf(bv.x, w.x, fmaf(bv.y, w.y, fmaf(bv.z, w.z, fmaf(bv.w, w.w, acc_b[e]))));
        }
    }
    #pragma unroll
    for (int e = 0; e < 4; e++) {
        float beta = fminf(fmaxf(acc_b[e] + 1.0f, 0.0f), 10.0f);
        g_pack[c * 512 + e0 + e] = make_float2(acc_a[e], -beta * 0.62133497f);  // -beta/ln5
    }
}

// ---------------- Main: causal elementwise sum ----------------
__global__ __launch_bounds__(256)
void hawkes_main(const int* __restrict__ concept_seq,      // [32,1024]
                 const int* __restrict__ question_seq,     // [32,1024]
                 const int* __restrict__ correctness_seq,  // [32,1024]
                 const int* __restrict__ time_seq,         // [32,1024]
                 const float* __restrict__ q_bias,         // [10000]
                 const float* __restrict__ c_bias,         // [256]
                 float* __restrict__ out)                  // [32,1023]
{
    constexpr int SEQ = 1024;
    extern __shared__ float2 sm2[];
    float2* Gs   = sm2;                  // [512][RS] -> (ga, gb) per (e, j-lane)
    float2* tse  = Gs + 512 * RS;        // [<=1024]  -> (time, e*RS as int bits)
    float*  jred = (float*)(tse + SEQ);  // [NJ]

    const int b   = blockIdx.y;
    const int j0  = ((int)gridDim.x - 1 - (int)blockIdx.x) * NJ;  // big tiles launch first
    const int tid = threadIdx.x;
    const int tj  = tid & (NJ - 1);      // 0..7
    const int si  = tid >> 3;            // 0..31
    const int iend = j0 + NJ;

    // Stage (time, row-offset) only for the i-range this CTA consumes
    for (int i = tid; i < iend; i += 256) {
        int g = b * SEQ + i;
        int e = concept_seq[g] + (correctness_seq[g] << 8);
        tse[i] = make_float2((float)time_seq[g], __int_as_float(e * RS));
    }
    if (tid < NJ) jred[tid] = 0.0f;

    // Gather packed rows for this CTA's NJ concepts: Gs[e][jl] <- g_pack[c_j][e]
    for (int idx = tid; idx < NJ * 256; idx += 256) {
        int jl = idx >> 8;               // 0..7
        int q  = idx & 255;              // float4 index (2 float2 entries)
        int cj = concept_seq[b * SEQ + j0 + jl];
        float4 v = ((const float4*)(g_pack + cj * 512))[q];
        Gs[(2 * q + 0) * RS + jl] = make_float2(v.x, v.y);
        Gs[(2 * q + 1) * RS + jl] = make_float2(v.z, v.w);
    }
    __syncthreads();

    const int   jg  = j0 + tj;
    const float tjv = tse[jg].x;
    float jsum = 0.0f;

    #pragma unroll 4
    for (int i = si; i < iend; i += 32) {
        float2 tv = tse[i];                              // LDS.64 (group broadcast)
        float2 g  = Gs[__float_as_int(tv.y) + tj];       // LDS.64, conflict-free
        float dt = fabsf(tv.x - tjv);
        float lg = __log2f(dt + 1e-10f);                 // MUFU.LG2
        float ex = fast_ex2(g.y * lg);                   // MUFU.EX2  = exp(-beta*log5(dt))
        jsum += (i < jg) ? g.x * ex : 0.0f;
    }

    // Reduce 32 i-slots -> per-j: fold groups within warp, then smem atomics
    jsum += __shfl_down_sync(0xffffffffu, jsum, 16);
    jsum += __shfl_down_sync(0xffffffffu, jsum, 8);
    if ((tid & 31) < NJ) atomicAdd(&jred[tj], jsum);
    __syncthreads();

    // Epilogue: bias + sigmoid; output drops j=0
    if (tid < NJ) {
        int j = j0 + tid;
        if (j > 0) {
            float x = q_bias[question_seq[b * SEQ + j]]
                    + c_bias[concept_seq[b * SEQ + j]]
                    + jred[tid];
            out[b * (SEQ - 1) + (j - 1)] = 1.0f / (1.0f + __expf(-x));
        }
    }
}

extern "C" void kernel_launch(void* const* d_in, const int* in_sizes, int n_in,
                              void* d_out, int out_size)
{
    (void)in_sizes; (void)n_in; (void)out_size;
    const int*   concept_seq     = (const int*)  d_in[0];
    const int*   question_seq    = (const int*)  d_in[1];
    const int*   correctness_seq = (const int*)  d_in[2];
    const int*   time_seq        = (const int*)  d_in[3];
    const float* a_inter         = (const float*)d_in[4];
    const float* a_concept       = (const float*)d_in[5];
    const float* b_inter         = (const float*)d_in[6];
    const float* b_concept       = (const float*)d_in[7];
    const float* q_bias          = (const float*)d_in[8];
    const float* c_bias          = (const float*)d_in[9];
    float* out = (float*)d_out;

    precompute_kernel<<<128, 256>>>(a_inter, a_concept, b_inter, b_concept);

    const int smem_bytes = (512 * RS + 1024) * (int)sizeof(float2) + NJ * (int)sizeof(float);
    cudaFuncSetAttribute(hawkes_main,
                         cudaFuncAttributeMaxDynamicSharedMemorySize, smem_bytes);
    dim3 grid(1024 / NJ, 32);   // (j-tiles, batches)
    hawkes_main<<<grid, 256, smem_bytes>>>(
        concept_seq, question_seq, correctness_seq, time_seq,
        q_bias, c_bias, out);
}